// round 6
// baseline (speedup 1.0000x reference)
#include <cuda_runtime.h>
#include <cuda_fp16.h>
#include <stdint.h>

#define THREADS 128
#define ROWS    32        // rows per block
#define PCOUNT  64        // predicates
#define EPAD    33        // E-table row stride (halves); 33 breaks phase-A store conflicts
#define C_MAX   128
#define NSPLIT  4         // clause quarters, one per warp
#define EROWS   128       // exp(+g_p) at row p, exp(-g_p)=rcp at row p+64
#define ENEG    (PCOUNT*EPAD)   // 2112: e-offsets >= this came from sign_bit==0

// Clause tables (built once per launch):
// g_t1[c] = {e0, e1, e2, a0}   e = (p + (sb?0:64))*EPAD (half units), a = p*32
// g_t2[c] = {a1, a2, float_bits(w), 0}
__device__ uint4 g_t1[C_MAX];
__device__ uint4 g_t2[C_MAX];

__device__ __forceinline__ float frcp(float x){ float y; asm("rcp.approx.f32 %0, %1;" : "=f"(y) : "f"(x)); return y; }
__device__ __forceinline__ float fex2(float x){ float y; asm("ex2.approx.f32 %0, %1;" : "=f"(y) : "f"(x)); return y; }

// literal_idx may physically be int32 (JAX x64-disabled) or int64; detect:
// int64 view of int32 data fuses two random indices -> out of [0,64) w.h.p.
__global__ void prep_kernel(const float* __restrict__ cw,
                            const void* __restrict__ litraw,
                            const int* __restrict__ sgn, int C)
{
    __shared__ int sh_is64;
    if (threadIdx.x == 0){
        const long long* v64 = (const long long*)litraw;
        int n = (C * 3) / 2;              // stays within int32-buffer bounds
        int ok = 1;
        for (int k = 0; k < n; k++){
            long long v = v64[k];
            if (v < 0 || v >= PCOUNT){ ok = 0; break; }
        }
        sh_is64 = ok;
    }
    __syncthreads();
    const int is64 = sh_is64;

    int c = blockIdx.x * blockDim.x + threadIdx.x;
    if (c >= C) return;
    float w = fminf(fmaxf(cw[c], 0.0f), 500.0f);     // clamp(0, 500)
    unsigned e[3], a[3];
    #pragma unroll
    for (int l = 0; l < 3; l++){
        int p = is64 ? (int)((const long long*)litraw)[c*3 + l]
                     :       ((const int*)litraw)[c*3 + l];
        int sb = sgn[c*3 + l];            // 1 -> +g half (weight +w), 0 -> -g half (weight -w)
        e[l] = (unsigned)((p + (sb ? 0 : PCOUNT)) * EPAD);
        a[l] = (unsigned)(p * ROWS);
    }
    g_t1[c] = make_uint4(e[0], e[1], e[2], a[0]);
    g_t2[c] = make_uint4(a[1], a[2], __float_as_uint(w), 0u);
}

__global__ void __launch_bounds__(THREADS)
main_kernel(const float* __restrict__ ga, float* __restrict__ out, int B)
{
    extern __shared__ char sh[];
    float*  __restrict__ A  = (float*)sh;                       // 4 copies * 64*32 f32 = 32768 B
    uint4*  T1 = (uint4*)(sh + NSPLIT*PCOUNT*ROWS*4);           // 2048 B
    uint4*  T2 = T1 + C_MAX;                                    // 2048 B
    __half* __restrict__ Eh = (__half*)(T2 + C_MAX);            // 128*33 halves = 8448 B

    const int tid  = threadIdx.x;
    const int lane = tid & 31;
    const int wrp  = tid >> 5;
    const long long rowbase = (long long)blockIdx.x * ROWS;
    long long rem = (long long)B - rowbase;
    const int nrows = rem < ROWS ? (int)rem : ROWS;
    const size_t base = (size_t)rowbase * PCOUNT;

    if (tid < C_MAX){ T1[tid] = g_t1[tid]; T2[tid] = g_t2[tid]; }

    // zero the 4 accumulator copies (vectorized)
    float4* A4 = (float4*)A;
    #pragma unroll
    for (int i = tid; i < NSPLIT*PCOUNT*ROWS/4; i += THREADS)
        A4[i] = make_float4(0.f, 0.f, 0.f, 0.f);

    // Phase A: coalesced 32x64 tile load; build fp16 exp table (exp(+g), rcp).
    const float4* ga4 = (const float4*)(ga + base);
    const float L2E = 1.4426950408889634f;
    #pragma unroll
    for (int i = tid; i < ROWS*PCOUNT/4; i += THREADS){
        int o = i * 4, row = o >> 6, p = o & (PCOUNT-1);
        if (row < nrows){
            float4 g = ga4[i];
            float t;
            t = fex2(g.x*L2E); Eh[(p  )*EPAD+row] = __float2half(t); Eh[(p+PCOUNT  )*EPAD+row] = __float2half(frcp(t));
            t = fex2(g.y*L2E); Eh[(p+1)*EPAD+row] = __float2half(t); Eh[(p+PCOUNT+1)*EPAD+row] = __float2half(frcp(t));
            t = fex2(g.z*L2E); Eh[(p+2)*EPAD+row] = __float2half(t); Eh[(p+PCOUNT+2)*EPAD+row] = __float2half(frcp(t));
            t = fex2(g.w*L2E); Eh[(p+3)*EPAD+row] = __float2half(t); Eh[(p+PCOUNT+3)*EPAD+row] = __float2half(frcp(t));
        }
    }
    __syncthreads();

    // Phase B: warp w owns clause quarter [32w, 32w+32) and private acc copy.
    // Thread handles row `lane`. Static trip count + unroll 8 => 8 independent
    // LDS/RMW chains in flight. All gathers/RMW are conflict-free (lane-consecutive).
    {
        float* __restrict__ Aw = A + wrp * (PCOUNT*ROWS);
        const int c0 = wrp * (C_MAX/NSPLIT);
        #pragma unroll 8
        for (int c = c0; c < c0 + C_MAX/NSPLIT; c++){
            uint4 t1 = T1[c], t2 = T2[c];
            int a0 = (int)t1.w, a1 = (int)t2.x, a2 = (int)t2.y;
            float w = __uint_as_float(t2.z);
            float w0 = (t1.x >= ENEG) ? -w : w;    // sign folded via E-half choice
            float w1 = (t1.y >= ENEG) ? -w : w;
            float w2 = (t1.z >= ENEG) ? -w : w;
            float x0 = __half2float(Eh[t1.x + lane]);
            float x1 = __half2float(Eh[t1.y + lane]);
            float x2 = __half2float(Eh[t1.z + lane]);
            float r  = frcp(x0 + x1 + x2);         // 1/sum(exp)
            Aw[a0 + lane] = fmaf(w0, x0*r, Aw[a0 + lane]);
            Aw[a1 + lane] = fmaf(w1, x1*r, Aw[a1 + lane]);
            Aw[a2 + lane] = fmaf(w2, x2*r, Aw[a2 + lane]);
        }
    }
    __syncthreads();

    // Reduce the 4 per-warp accumulator copies into copy 0 (vectorized).
    {
        const int n4 = PCOUNT*ROWS/4;   // 512
        #pragma unroll
        for (int i = tid; i < n4; i += THREADS){
            float4 a = A4[i], b = A4[i + n4], c = A4[i + 2*n4], d = A4[i + 3*n4];
            a.x += b.x + c.x + d.x;
            a.y += b.y + c.y + d.y;
            a.z += b.z + c.z + d.z;
            a.w += b.w + c.w + d.w;
            A4[i] = a;
        }
    }
    __syncthreads();

    // Phase C: thread (q=tid>>5, row=lane) handles predicate quarter q.
    // Smem reads are lane-consecutive (conflict-free); stores are per-lane
    // STG.128 at 256B lane stride (50% sector efficiency -- DRAM has slack).
    {
        const int q = wrp;          // predicate quarter
        const int row = lane;
        if (row < nrows){
            float4* out4 = (float4*)(out + base + (size_t)row * PCOUNT);
            #pragma unroll
            for (int j = 0; j < 4; j++){
                int pb = q*16 + j*4;
                float4 v;
                v.x = A[(pb  )*ROWS + row];
                v.y = A[(pb+1)*ROWS + row];
                v.z = A[(pb+2)*ROWS + row];
                v.w = A[(pb+3)*ROWS + row];
                out4[pb >> 2] = v;
            }
        }
    }
}

extern "C" void kernel_launch(void* const* d_in, const int* in_sizes, int n_in,
                              void* d_out, int out_size)
{
    const float* ga  = (const float*)d_in[0];      // ground_atoms [B,64] f32
    const float* cw  = (const float*)d_in[1];      // clause_weights [C] f32
    const void*  lit = d_in[2];                    // literal_idx [C,3] i32-or-i64
    const int*   sgn = (const int*)d_in[3];        // sign_bits [C,3] i32
    float* out = (float*)d_out;

    int C = in_sizes[1];
    int B = in_sizes[0] / PCOUNT;
    int nblocks = (B + ROWS - 1) / ROWS;
    size_t smem = (size_t)NSPLIT*PCOUNT*ROWS*4            // acc: 32768
                + 2 * C_MAX * sizeof(uint4)               // tables: 4096
                + (size_t)EROWS*EPAD*2;                   // fp16 E: 8448  => 45312 B

    cudaFuncSetAttribute(main_kernel, cudaFuncAttributeMaxDynamicSharedMemorySize, (int)smem);
    prep_kernel<<<1, THREADS>>>(cw, lit, sgn, C);
    main_kernel<<<nblocks, THREADS, smem>>>(ga, out, B);
}